// round 2
// baseline (speedup 1.0000x reference)
#include <cuda_runtime.h>
#include <cstdint>

// SPLoPAdapter: out[i*32+a, j*32+b] = weights[.] + sum_k pos[k,i,j]*w[k,a]*h[k,b]
// weights (2048,2048) f32; pos (64,64,64); proto_w (64,32); proto_h (64,32)
//
// CTA = 4x4 block of 32x32 tiles (128x128 output region), 128 threads.
// Thread: one tile, 16(a) x 8(b) patch. acc in f32x2 (fma.rn.f32x2).
// Per k: scale h-pairs by pos (mul.rn.f32x2), dup w scalars, 64 FMA2.

#define FMA2(acc, av, bv) \
    asm("fma.rn.f32x2 %0, %1, %2, %3;" : "=l"(acc) : "l"(av), "l"(bv), "l"(acc))
#define MUL2(dst, av, bv) \
    asm("mul.rn.f32x2 %0, %1, %2;" : "=l"(dst) : "l"(av), "l"(bv))
#define ADD2(dst, av, bv) \
    asm("add.rn.f32x2 %0, %1, %2;" : "=l"(dst) : "l"(av), "l"(bv))
#define DUP(dst, s) \
    asm("mov.b64 %0, {%1, %1};" : "=l"(dst) : "r"(__float_as_uint(s)))

__global__ void __launch_bounds__(128) splopa_kernel(
    const float* __restrict__ weights,
    const float* __restrict__ pos,
    const float* __restrict__ pw,
    const float* __restrict__ ph,
    float* __restrict__ out)
{
    __shared__ float ws[2048];        // w[k][a]   (8 KB)
    __shared__ float hs[2048];        // h[k][b]   (8 KB)
    __shared__ float ps_s[64][16];    // pos[k][tile] (4 KB)

    const int tid = threadIdx.x;
    const int bi = blockIdx.y;
    const int bj = blockIdx.x;

    // load w, h (512 float4 each, 128 threads -> 4 each)
    #pragma unroll
    for (int i = 0; i < 4; i++) {
        ((float4*)ws)[tid + i * 128] = ((const float4*)pw)[tid + i * 128];
        ((float4*)hs)[tid + i * 128] = ((const float4*)ph)[tid + i * 128];
    }
    // load pos for the 16 tiles: tile t = (ti,tj) = (t>>2, t&3)
    #pragma unroll
    for (int i = 0; i < 8; i++) {
        const int idx = tid + i * 128;
        const int t = idx & 15;
        const int k = idx >> 4;
        ps_s[k][t] = pos[k * 4096 + (bi * 4 + (t >> 2)) * 64 + bj * 4 + (t & 3)];
    }
    __syncthreads();

    const int t  = tid >> 3;          // tile 0..15
    const int q  = tid & 7;           // 8 threads per tile
    const int a0 = (q >> 2) * 16;     // row base within tile (0 or 16)
    const int b0 = (q & 3) * 8;       // col base within tile (0,8,16,24)

    unsigned long long acc[16][4];
    #pragma unroll
    for (int a = 0; a < 16; a++)
        #pragma unroll
        for (int j = 0; j < 4; j++)
            acc[a][j] = 0ull;

    #pragma unroll 4
    for (int k = 0; k < 64; k++) {
        const float psv = ps_s[k][t];
        unsigned long long ps2;
        DUP(ps2, psv);

        const ulonglong2 ha = *(const ulonglong2*)&hs[k * 32 + b0];
        const ulonglong2 hb = *(const ulonglong2*)&hs[k * 32 + b0 + 4];
        unsigned long long hp[4];
        MUL2(hp[0], ha.x, ps2);
        MUL2(hp[1], ha.y, ps2);
        MUL2(hp[2], hb.x, ps2);
        MUL2(hp[3], hb.y, ps2);

        #pragma unroll
        for (int i = 0; i < 4; i++) {
            const float4 wv = *(const float4*)&ws[k * 32 + a0 + i * 4];
            unsigned long long d;
            DUP(d, wv.x);
            FMA2(acc[i*4+0][0], d, hp[0]); FMA2(acc[i*4+0][1], d, hp[1]);
            FMA2(acc[i*4+0][2], d, hp[2]); FMA2(acc[i*4+0][3], d, hp[3]);
            DUP(d, wv.y);
            FMA2(acc[i*4+1][0], d, hp[0]); FMA2(acc[i*4+1][1], d, hp[1]);
            FMA2(acc[i*4+1][2], d, hp[2]); FMA2(acc[i*4+1][3], d, hp[3]);
            DUP(d, wv.z);
            FMA2(acc[i*4+2][0], d, hp[0]); FMA2(acc[i*4+2][1], d, hp[1]);
            FMA2(acc[i*4+2][2], d, hp[2]); FMA2(acc[i*4+2][3], d, hp[3]);
            DUP(d, wv.w);
            FMA2(acc[i*4+3][0], d, hp[0]); FMA2(acc[i*4+3][1], d, hp[1]);
            FMA2(acc[i*4+3][2], d, hp[2]); FMA2(acc[i*4+3][3], d, hp[3]);
        }
    }

    // epilogue: out = weights + acc  (16 rows x 8 cols per thread)
    const int row0 = (bi * 4 + (t >> 2)) * 32 + a0;
    const int col0 = (bj * 4 + (t & 3)) * 32 + b0;

    #pragma unroll
    for (int a = 0; a < 16; a++) {
        const size_t off = (size_t)(row0 + a) * 2048 + col0;
        const ulonglong2 w0 = *(const ulonglong2*)(weights + off);
        const ulonglong2 w1 = *(const ulonglong2*)(weights + off + 4);
        ulonglong2 o0, o1;
        ADD2(o0.x, w0.x, acc[a][0]);
        ADD2(o0.y, w0.y, acc[a][1]);
        ADD2(o1.x, w1.x, acc[a][2]);
        ADD2(o1.y, w1.y, acc[a][3]);
        *(ulonglong2*)(out + off)     = o0;
        *(ulonglong2*)(out + off + 4) = o1;
    }
}

extern "C" void kernel_launch(void* const* d_in, const int* in_sizes, int n_in,
                              void* d_out, int out_size)
{
    const float* weights = (const float*)d_in[0];
    const float* pos     = (const float*)d_in[1];
    const float* pw      = (const float*)d_in[2];
    const float* ph      = (const float*)d_in[3];
    float* out           = (float*)d_out;

    dim3 grid(16, 16);   // each CTA: 4x4 tiles of 32x32 = 128x128 outputs
    dim3 block(128);
    splopa_kernel<<<grid, block>>>(weights, pos, pw, ph, out);
}